// round 9
// baseline (speedup 1.0000x reference)
#include <cuda_runtime.h>
#include <cuda_bf16.h>
#include <math.h>
#include <stdint.h>

#define T_TOK 8192
#define H 1024
#define E 8
#define CAP 1024   // capacity = T/E

// ---------------- scratch (no allocations allowed) ----------------
__device__ int   g_expert_idx[T_TOK];
__device__ float g_gate[T_TOK];
__device__ int   g_slot_token[E * CAP];   // token id per (expert, slot), -1 if empty
__device__ unsigned char g_dropped[T_TOK];
__device__ __align__(256) __nv_bfloat16 g_Whi[E * H * H];   // 16 MB
__device__ __align__(256) __nv_bfloat16 g_Wlo[E * H * H];   // 16 MB
__device__ __align__(256) __nv_bfloat16 g_Ahi[T_TOK * H];   // 16 MB (gathered per-slot x)
__device__ __align__(256) __nv_bfloat16 g_Alo[T_TOK * H];   // 16 MB

// ---------------- kernel 1: routing ----------------
__global__ void route_kernel(const float* __restrict__ x,
                             const float* __restrict__ wg) {
    __shared__ float s_wg[H * E];
    for (int i = threadIdx.x; i < H * E; i += blockDim.x) s_wg[i] = wg[i];
    __syncthreads();

    int warp = (blockIdx.x * blockDim.x + threadIdx.x) >> 5;
    int lane = threadIdx.x & 31;
    if (warp >= T_TOK) return;

    const float* xp = x + (size_t)warp * H;
    float acc[E];
#pragma unroll
    for (int e = 0; e < E; e++) acc[e] = 0.f;
    for (int k = lane; k < H; k += 32) {
        float xv = xp[k];
        const float* w = s_wg + k * E;
#pragma unroll
        for (int e = 0; e < E; e++) acc[e] = fmaf(xv, w[e], acc[e]);
    }
#pragma unroll
    for (int e = 0; e < E; e++) {
#pragma unroll
        for (int o = 16; o > 0; o >>= 1)
            acc[e] += __shfl_down_sync(0xffffffffu, acc[e], o);
    }
    if (lane == 0) {
        float m = acc[0]; int bi = 0;
#pragma unroll
        for (int e = 1; e < E; e++)
            if (acc[e] > m) { m = acc[e]; bi = e; }
        float s = 0.f;
#pragma unroll
        for (int e = 0; e < E; e++) s += expf(acc[e] - m);
        g_expert_idx[warp] = bi;
        g_gate[warp]       = 1.f / s;
    }
}

// ---------------- kernel 2: order-preserving scan (warp-shuffle) ----------------
__global__ void scan_kernel() {
    __shared__ unsigned long long w0[32], w1[32];
    const int tid = threadIdx.x;
    const int lane = tid & 31, wid = tid >> 5;

    const int base = tid * 8;
    int eidx[8];
    unsigned long long c0 = 0ULL, c1 = 0ULL;
#pragma unroll
    for (int j = 0; j < 8; j++) {
        int e = g_expert_idx[base + j];
        eidx[j] = e;
        if (e < 4) c0 += 1ULL << (16 * e);
        else       c1 += 1ULL << (16 * (e - 4));
    }
    unsigned long long s0 = c0, s1 = c1;
#pragma unroll
    for (int d = 1; d < 32; d <<= 1) {
        unsigned long long t0 = __shfl_up_sync(0xffffffffu, s0, d);
        unsigned long long t1 = __shfl_up_sync(0xffffffffu, s1, d);
        if (lane >= d) { s0 += t0; s1 += t1; }
    }
    if (lane == 31) { w0[wid] = s0; w1[wid] = s1; }

    for (int i = tid; i < E * CAP; i += 1024) g_slot_token[i] = -1;
    __syncthreads();
    if (wid == 0) {
        unsigned long long v0 = w0[lane], v1 = w1[lane];
#pragma unroll
        for (int d = 1; d < 32; d <<= 1) {
            unsigned long long t0 = __shfl_up_sync(0xffffffffu, v0, d);
            unsigned long long t1 = __shfl_up_sync(0xffffffffu, v1, d);
            if (lane >= d) { v0 += t0; v1 += t1; }
        }
        w0[lane] = v0; w1[lane] = v1;
    }
    __syncthreads();
    unsigned long long o0 = s0 - c0 + (wid > 0 ? w0[wid - 1] : 0ULL);
    unsigned long long o1 = s1 - c1 + (wid > 0 ? w1[wid - 1] : 0ULL);

    int off[E];
#pragma unroll
    for (int e = 0; e < 4; e++) {
        off[e]     = (int)((o0 >> (16 * e)) & 0xFFFFULL);
        off[e + 4] = (int)((o1 >> (16 * e)) & 0xFFFFULL);
    }
#pragma unroll
    for (int j = 0; j < 8; j++) {
        int t = base + j;
        int e = eidx[j];
        int p = 0;
#pragma unroll
        for (int q = 0; q < E; q++)
            if (e == q) { p = off[q]; off[q] = p + 1; }
        if (p < CAP) { g_slot_token[e * CAP + p] = t; g_dropped[t] = 0; }
        else         { g_dropped[t] = 1; }
    }
}

// ---------------- kernel 3: zero only dropped-token rows ----------------
__global__ void zero_drop_kernel(float* __restrict__ out) {
    int t = blockIdx.x;
    if (!g_dropped[t]) return;
    float4* row = (float4*)(out + (size_t)t * H);
    row[threadIdx.x]       = make_float4(0.f, 0.f, 0.f, 0.f);
    row[threadIdx.x + 128] = make_float4(0.f, 0.f, 0.f, 0.f);
}

// ---------------- hi/lo bf16 split helpers ----------------
__device__ __forceinline__ void split8(const float4 a, const float4 b,
                                       uint4& hi, uint4& lo) {
    float v[8] = {a.x, a.y, a.z, a.w, b.x, b.y, b.z, b.w};
    __nv_bfloat16 h[8], l[8];
#pragma unroll
    for (int i = 0; i < 8; i++) {
        h[i] = __float2bfloat16(v[i]);
        l[i] = __float2bfloat16(v[i] - __bfloat162float(h[i]));
    }
    hi = *(uint4*)h;
    lo = *(uint4*)l;
}

// ---------------- kernel 4: fused convert W + gather/convert A ----------------
// blocks [0, 8192): W rows; blocks [8192, 16384): A slot rows. 128 threads.
__global__ void conv_kernel(const float* __restrict__ W, const float* __restrict__ x) {
    int bid = blockIdx.x;
    if (bid < 8192) {
        // each block converts 1024 W elements (one H-row)
        size_t base = (size_t)bid * 1024 + threadIdx.x * 8;
        float4 a = *(const float4*)(W + base);
        float4 b = *(const float4*)(W + base + 4);
        uint4 hi, lo;
        split8(a, b, hi, lo);
        *(uint4*)(g_Whi + base) = hi;
        *(uint4*)(g_Wlo + base) = lo;
    } else {
        int r = bid - 8192;                 // slot row 0..8191
        int tok = g_slot_token[r];
        size_t base = (size_t)r * H + threadIdx.x * 8;
        if (tok < 0) {
            uint4 z = make_uint4(0, 0, 0, 0);
            *(uint4*)(g_Ahi + base) = z;
            *(uint4*)(g_Alo + base) = z;
            return;
        }
        const float* xr = x + (size_t)tok * H + threadIdx.x * 8;
        float4 a = *(const float4*)xr;
        float4 b = *(const float4*)(xr + 4);
        uint4 hi, lo;
        split8(a, b, hi, lo);
        *(uint4*)(g_Ahi + base) = hi;
        *(uint4*)(g_Alo + base) = lo;
    }
}

// ---------------- kernel 5: GEMM, 512 thr, 3-stage cp.async (2-chunk cover) ----------------
#define BM 128
#define BN 128
#define BK 64                      // bf16 per chunk = 128B rows
#define KITER (H / BK)             // 16
#define ROW_B 128                  // bytes per smem row
#define PLANE_B (BM * ROW_B)       // 16384
#define STAGE_B (4 * PLANE_B)      // 65536
#define NSTAGE 3
#define SMEM_TOK 512
#define GEMM_SMEM (SMEM_TOK + NSTAGE * STAGE_B)   // 197120

__device__ __forceinline__ uint32_t smem_u32(const void* p) {
    uint32_t a;
    asm("{ .reg .u64 t; cvta.to.shared.u64 t, %1; cvt.u32.u64 %0, t; }" : "=r"(a) : "l"(p));
    return a;
}
__device__ __forceinline__ void cpasync16(uint32_t dst, const void* src) {
    asm volatile("cp.async.cg.shared.global [%0], [%1], 16;" :: "r"(dst), "l"(src));
}
__device__ __forceinline__ void ldsm4(uint32_t& r0, uint32_t& r1, uint32_t& r2, uint32_t& r3,
                                      uint32_t addr) {
    asm volatile("ldmatrix.sync.aligned.m8n8.x4.shared.b16 {%0,%1,%2,%3}, [%4];"
                 : "=r"(r0), "=r"(r1), "=r"(r2), "=r"(r3) : "r"(addr));
}
__device__ __forceinline__ void mma16816(float* d, const uint32_t* a, uint32_t b0, uint32_t b1) {
    asm volatile("mma.sync.aligned.m16n8k16.row.col.f32.bf16.bf16.f32 "
                 "{%0,%1,%2,%3}, {%4,%5,%6,%7}, {%8,%9}, {%0,%1,%2,%3};"
                 : "+f"(d[0]), "+f"(d[1]), "+f"(d[2]), "+f"(d[3])
                 : "r"(a[0]), "r"(a[1]), "r"(a[2]), "r"(a[3]), "r"(b0), "r"(b1));
}

__global__ void __launch_bounds__(512, 1)
moe_gemm(const float* __restrict__ bias, float* __restrict__ out) {
    extern __shared__ char smem[];
    int* s_tok = (int*)smem;
    const uint32_t sbase = smem_u32(smem) + SMEM_TOK;

    const int tid  = threadIdx.x;
    const int lane = tid & 31;
    const int wid  = tid >> 5;             // 0..15, warp grid 4(M) x 4(N)
    const int bm = blockIdx.y * BM;
    const int bn = blockIdx.x * BN;
    const int e  = bm >> 10;

    if (tid < BM) s_tok[tid] = g_slot_token[bm + tid];

    // ---- cp.async mapping: row = tid>>2 (4 thr/row), 2 x 16B segs each ----
    const int crow = tid >> 2;
    const int s0   = (tid & 3) * 2;
    const uint32_t d0 = (uint32_t)(crow * ROW_B + ((s0     ^ (crow & 7)) * 16));
    const uint32_t d1 = (uint32_t)(crow * ROW_B + (((s0+1) ^ (crow & 7)) * 16));
    const __nv_bfloat16* pAhi = g_Ahi + (size_t)(bm + crow) * H + s0 * 8;
    const __nv_bfloat16* pAlo = g_Alo + (size_t)(bm + crow) * H + s0 * 8;
    const __nv_bfloat16* pBhi = g_Whi + ((size_t)e * H + bn + crow) * H + s0 * 8;
    const __nv_bfloat16* pBlo = g_Wlo + ((size_t)e * H + bn + crow) * H + s0 * 8;

#define ISSUE_STAGE(stg, kc) do { \
        uint32_t db = sbase + (stg) * STAGE_B; \
        int ko = (kc) * BK; \
        cpasync16(db + d0,               pAhi + ko); \
        cpasync16(db + d1,               pAhi + ko + 8); \
        cpasync16(db + PLANE_B + d0,     pAlo + ko); \
        cpasync16(db + PLANE_B + d1,     pAlo + ko + 8); \
        cpasync16(db + 2*PLANE_B + d0,   pBhi + ko); \
        cpasync16(db + 2*PLANE_B + d1,   pBhi + ko + 8); \
        cpasync16(db + 3*PLANE_B + d0,   pBlo + ko); \
        cpasync16(db + 3*PLANE_B + d1,   pBlo + ko + 8); \
        asm volatile("cp.async.commit_group;" ::: "memory"); \
    } while (0)

    float D[2][4][4];
#pragma unroll
    for (int mt = 0; mt < 2; mt++)
#pragma unroll
        for (int nt = 0; nt < 4; nt++)
#pragma unroll
            for (int r = 0; r < 4; r++) D[mt][nt][r] = 0.f;

    const int mrow = (wid >> 2) * 32 + (lane & 15);   // + mt*16
    const int nrow = (wid & 3) * 32 + (lane & 15);    // + np*16
    const int chalf = lane >> 4;                      // 16B half within k16

    // fill the whole 3-stage pipe up front -> every copy gets ~2 chunks of cover
    ISSUE_STAGE(0, 0);
    ISSUE_STAGE(1, 1);
    ISSUE_STAGE(2, 2);

    for (int kc = 0; kc < KITER; kc++) {
        // wait until group kc is complete (count = groups issued after kc)
        if (kc < KITER - 2)      asm volatile("cp.async.wait_group 2;" ::: "memory");
        else if (kc == KITER - 2) asm volatile("cp.async.wait_group 1;" ::: "memory");
        else                      asm volatile("cp.async.wait_group 0;" ::: "memory");
        __syncthreads();

        const uint32_t ab = sbase + (kc % NSTAGE) * STAGE_B;
#pragma unroll
        for (int ks = 0; ks < 4; ks++) {
            const int seg = ks * 2 + chalf;
            uint32_t ahi[2][4], alo[2][4], bh[2][4], bl[2][4];
#pragma unroll
            for (int mt = 0; mt < 2; mt++) {
                int r = mrow + mt * 16;
                uint32_t ad = ab + r * ROW_B + ((seg ^ (r & 7)) * 16);
                ldsm4(ahi[mt][0], ahi[mt][1], ahi[mt][2], ahi[mt][3], ad);
                ldsm4(alo[mt][0], alo[mt][1], alo[mt][2], alo[mt][3], ad + PLANE_B);
            }
#pragma unroll
            for (int np = 0; np < 2; np++) {
                int r = nrow + np * 16;
                uint32_t bd = ab + 2 * PLANE_B + r * ROW_B + ((seg ^ (r & 7)) * 16);
                ldsm4(bh[np][0], bh[np][1], bh[np][2], bh[np][3], bd);
                ldsm4(bl[np][0], bl[np][1], bl[np][2], bl[np][3], bd + PLANE_B);
            }
            // term-outer ordering: same-accumulator reuse distance = 8 MMAs
#pragma unroll
            for (int t = 0; t < 3; t++)
#pragma unroll
                for (int mt = 0; mt < 2; mt++)
#pragma unroll
                    for (int nt = 0; nt < 4; nt++) {
                        int np = nt >> 1, od = nt & 1;
                        if (t == 0)
                            mma16816(D[mt][nt], ahi[mt], bh[np][od], bh[np][2 + od]);
                        else if (t == 1)
                            mma16816(D[mt][nt], ahi[mt], bl[np][od], bl[np][2 + od]);
                        else
                            mma16816(D[mt][nt], alo[mt], bh[np][od], bh[np][2 + od]);
                    }
        }
        __syncthreads();   // all warps done reading stage kc%3
        if (kc + 3 < KITER) ISSUE_STAGE(kc % NSTAGE, kc + 3);
    }

    // ---- epilogue: gate * (D + bias) scattered to token rows ----
    const int wm = (wid >> 2) * 32;
    const int wn = (wid & 3) * 32;
#pragma unroll
    for (int mt = 0; mt < 2; mt++) {
#pragma unroll
        for (int half = 0; half < 2; half++) {
            int r = wm + mt * 16 + (lane >> 2) + half * 8;
            int tok = s_tok[r];
            if (tok < 0) continue;
            float g = g_gate[tok];
            float* orow = out + (size_t)tok * H + bn + wn;
#pragma unroll
            for (int nt = 0; nt < 4; nt++) {
                int c = nt * 8 + (lane & 3) * 2;
                float2 bb = *(const float2*)(bias + (size_t)e * H + bn + wn + c);
                float2 v;
                v.x = g * (D[mt][nt][half * 2 + 0] + bb.x);
                v.y = g * (D[mt][nt][half * 2 + 1] + bb.y);
                *(float2*)(orow + c) = v;
            }
        }
    }
}

extern "C" void kernel_launch(void* const* d_in, const int* in_sizes, int n_in,
                              void* d_out, int out_size) {
    const float* x  = (const float*)d_in[0];   // [T, H]
    const float* wg = (const float*)d_in[1];   // [H, E]
    const float* W  = (const float*)d_in[2];   // [E, H, H]
    const float* b  = (const float*)d_in[3];   // [E, H]
    float* out = (float*)d_out;                // [T, H]

    cudaFuncSetAttribute(moe_gemm, cudaFuncAttributeMaxDynamicSharedMemorySize, GEMM_SMEM);

    route_kernel<<<T_TOK / 8, 256>>>(x, wg);
    scan_kernel<<<1, 1024>>>();
    conv_kernel<<<16384, 128>>>(W, x);
    zero_drop_kernel<<<T_TOK, 128>>>(out);
    dim3 grid(H / BN, T_TOK / BM);             // (8, 64)
    moe_gemm<<<grid, 512, GEMM_SMEM>>>(b, out);
}

// round 10
// speedup vs baseline: 1.3007x; 1.3007x over previous
#include <cuda_runtime.h>
#include <cuda_fp16.h>
#include <math.h>
#include <stdint.h>

#define T_TOK 8192
#define H 1024
#define E 8
#define CAP 1024   // capacity = T/E
#define WSCALE 64.0f
#define INV_WSCALE (1.0f / 64.0f)

// ---------------- scratch (no allocations allowed) ----------------
__device__ int   g_expert_idx[T_TOK];
__device__ float g_gate[T_TOK];
__device__ int   g_slot_token[E * CAP];   // token id per (expert, slot), -1 if empty
__device__ unsigned char g_dropped[T_TOK];
__device__ __align__(256) __half g_Whi[E * H * H];   // 16 MB (fp16 of 64*W)
__device__ __align__(256) __half g_Wlo[E * H * H];   // 16 MB (residual)
__device__ __align__(256) __half g_Ahi[T_TOK * H];   // 16 MB (gathered per-slot x, fp16)

// ---------------- kernel 1: routing ----------------
__global__ void route_kernel(const float* __restrict__ x,
                             const float* __restrict__ wg) {
    __shared__ float s_wg[H * E];
    for (int i = threadIdx.x; i < H * E; i += blockDim.x) s_wg[i] = wg[i];
    __syncthreads();

    int warp = (blockIdx.x * blockDim.x + threadIdx.x) >> 5;
    int lane = threadIdx.x & 31;
    if (warp >= T_TOK) return;

    const float* xp = x + (size_t)warp * H;
    float acc[E];
#pragma unroll
    for (int e = 0; e < E; e++) acc[e] = 0.f;
    for (int k = lane; k < H; k += 32) {
        float xv = xp[k];
        const float* w = s_wg + k * E;
#pragma unroll
        for (int e = 0; e < E; e++) acc[e] = fmaf(xv, w[e], acc[e]);
    }
#pragma unroll
    for (int e = 0; e < E; e++) {
#pragma unroll
        for (int o = 16; o > 0; o >>= 1)
            acc[e] += __shfl_down_sync(0xffffffffu, acc[e], o);
    }
    if (lane == 0) {
        float m = acc[0]; int bi = 0;
#pragma unroll
        for (int e = 1; e < E; e++)
            if (acc[e] > m) { m = acc[e]; bi = e; }
        float s = 0.f;
#pragma unroll
        for (int e = 0; e < E; e++) s += expf(acc[e] - m);
        g_expert_idx[warp] = bi;
        g_gate[warp]       = 1.f / s;
    }
}

// ---------------- kernel 2: order-preserving scan (warp-shuffle) ----------------
__global__ void scan_kernel() {
    __shared__ unsigned long long w0[32], w1[32];
    const int tid = threadIdx.x;
    const int lane = tid & 31, wid = tid >> 5;

    const int base = tid * 8;
    int eidx[8];
    unsigned long long c0 = 0ULL, c1 = 0ULL;
#pragma unroll
    for (int j = 0; j < 8; j++) {
        int e = g_expert_idx[base + j];
        eidx[j] = e;
        if (e < 4) c0 += 1ULL << (16 * e);
        else       c1 += 1ULL << (16 * (e - 4));
    }
    unsigned long long s0 = c0, s1 = c1;
#pragma unroll
    for (int d = 1; d < 32; d <<= 1) {
        unsigned long long t0 = __shfl_up_sync(0xffffffffu, s0, d);
        unsigned long long t1 = __shfl_up_sync(0xffffffffu, s1, d);
        if (lane >= d) { s0 += t0; s1 += t1; }
    }
    if (lane == 31) { w0[wid] = s0; w1[wid] = s1; }

    for (int i = tid; i < E * CAP; i += 1024) g_slot_token[i] = -1;
    __syncthreads();
    if (wid == 0) {
        unsigned long long v0 = w0[lane], v1 = w1[lane];
#pragma unroll
        for (int d = 1; d < 32; d <<= 1) {
            unsigned long long t0 = __shfl_up_sync(0xffffffffu, v0, d);
            unsigned long long t1 = __shfl_up_sync(0xffffffffu, v1, d);
            if (lane >= d) { v0 += t0; v1 += t1; }
        }
        w0[lane] = v0; w1[lane] = v1;
    }
    __syncthreads();
    unsigned long long o0 = s0 - c0 + (wid > 0 ? w0[wid - 1] : 0ULL);
    unsigned long long o1 = s1 - c1 + (wid > 0 ? w1[wid - 1] : 0ULL);

    int off[E];
#pragma unroll
    for (int e = 0; e < 4; e++) {
        off[e]     = (int)((o0 >> (16 * e)) & 0xFFFFULL);
        off[e + 4] = (int)((o1 >> (16 * e)) & 0xFFFFULL);
    }
#pragma unroll
    for (int j = 0; j < 8; j++) {
        int t = base + j;
        int e = eidx[j];
        int p = 0;
#pragma unroll
        for (int q = 0; q < E; q++)
            if (e == q) { p = off[q]; off[q] = p + 1; }
        if (p < CAP) { g_slot_token[e * CAP + p] = t; g_dropped[t] = 0; }
        else         { g_dropped[t] = 1; }
    }
}

// ---------------- kernel 3: fused convert W (hi/lo fp16 of 64*W), gather A, zero dropped ----------------
// blocks [0, 8192): W rows; [8192, 16384): A slot rows; [16384, 24576): dropped-token zeroing
__global__ void conv_kernel(const float* __restrict__ W, const float* __restrict__ x,
                            float* __restrict__ out) {
    int bid = blockIdx.x;
    if (bid < 8192) {
        size_t base = (size_t)bid * 1024 + threadIdx.x * 8;
        float4 a = *(const float4*)(W + base);
        float4 b = *(const float4*)(W + base + 4);
        float v[8] = {a.x, a.y, a.z, a.w, b.x, b.y, b.z, b.w};
        __half hi[8], lo[8];
#pragma unroll
        for (int i = 0; i < 8; i++) {
            float s = v[i] * WSCALE;
            hi[i] = __float2half_rn(s);
            lo[i] = __float2half_rn(s - __half2float(hi[i]));
        }
        *(uint4*)(g_Whi + base) = *(uint4*)hi;
        *(uint4*)(g_Wlo + base) = *(uint4*)lo;
    } else if (bid < 16384) {
        int r = bid - 8192;                 // slot row 0..8191
        int tok = g_slot_token[r];
        size_t base = (size_t)r * H + threadIdx.x * 8;
        if (tok < 0) {
            *(uint4*)(g_Ahi + base) = make_uint4(0, 0, 0, 0);
            return;
        }
        const float* xr = x + (size_t)tok * H + threadIdx.x * 8;
        float4 a = *(const float4*)xr;
        float4 b = *(const float4*)(xr + 4);
        float v[8] = {a.x, a.y, a.z, a.w, b.x, b.y, b.z, b.w};
        __half h[8];
#pragma unroll
        for (int i = 0; i < 8; i++) h[i] = __float2half_rn(v[i]);
        *(uint4*)(g_Ahi + base) = *(uint4*)h;
    } else {
        int t = bid - 16384;
        if (!g_dropped[t]) return;
        float4* row = (float4*)(out + (size_t)t * H);
        row[threadIdx.x]       = make_float4(0.f, 0.f, 0.f, 0.f);
        row[threadIdx.x + 128] = make_float4(0.f, 0.f, 0.f, 0.f);
    }
}

// ---------------- kernel 4: GEMM, fp16 2-term, 3 planes, 4-stage cp.async ----------------
#define BM 128
#define BN 128
#define BK 64                      // fp16 per chunk = 128B rows
#define KITER (H / BK)             // 16
#define ROW_B 128                  // bytes per smem row
#define PLANE_B (BM * ROW_B)       // 16384
#define STAGE_B (3 * PLANE_B)      // 49152
#define NSTAGE 4
#define SMEM_TOK 512
#define GEMM_SMEM (SMEM_TOK + NSTAGE * STAGE_B)   // 197120

__device__ __forceinline__ uint32_t smem_u32(const void* p) {
    uint32_t a;
    asm("{ .reg .u64 t; cvta.to.shared.u64 t, %1; cvt.u32.u64 %0, t; }" : "=r"(a) : "l"(p));
    return a;
}
__device__ __forceinline__ void cpasync16(uint32_t dst, const void* src) {
    asm volatile("cp.async.cg.shared.global [%0], [%1], 16;" :: "r"(dst), "l"(src));
}
__device__ __forceinline__ void ldsm4(uint32_t& r0, uint32_t& r1, uint32_t& r2, uint32_t& r3,
                                      uint32_t addr) {
    asm volatile("ldmatrix.sync.aligned.m8n8.x4.shared.b16 {%0,%1,%2,%3}, [%4];"
                 : "=r"(r0), "=r"(r1), "=r"(r2), "=r"(r3) : "r"(addr));
}
__device__ __forceinline__ void mma16816(float* d, const uint32_t* a, uint32_t b0, uint32_t b1) {
    asm volatile("mma.sync.aligned.m16n8k16.row.col.f32.f16.f16.f32 "
                 "{%0,%1,%2,%3}, {%4,%5,%6,%7}, {%8,%9}, {%0,%1,%2,%3};"
                 : "+f"(d[0]), "+f"(d[1]), "+f"(d[2]), "+f"(d[3])
                 : "r"(a[0]), "r"(a[1]), "r"(a[2]), "r"(a[3]), "r"(b0), "r"(b1));
}

__global__ void __launch_bounds__(512, 1)
moe_gemm(const float* __restrict__ bias, float* __restrict__ out) {
    extern __shared__ char smem[];
    int* s_tok = (int*)smem;
    const uint32_t sbase = smem_u32(smem) + SMEM_TOK;

    const int tid  = threadIdx.x;
    const int lane = tid & 31;
    const int wid  = tid >> 5;             // 0..15, warp grid 4(M) x 4(N)
    const int bm = blockIdx.y * BM;
    const int bn = blockIdx.x * BN;
    const int e  = bm >> 10;

    if (tid < BM) s_tok[tid] = g_slot_token[bm + tid];

    // ---- cp.async mapping: row = tid>>2 (4 thr/row), 2 x 16B segs each ----
    const int crow = tid >> 2;
    const int s0   = (tid & 3) * 2;
    const uint32_t d0 = (uint32_t)(crow * ROW_B + ((s0     ^ (crow & 7)) * 16));
    const uint32_t d1 = (uint32_t)(crow * ROW_B + (((s0+1) ^ (crow & 7)) * 16));
    const __half* pAhi = g_Ahi + (size_t)(bm + crow) * H + s0 * 8;
    const __half* pBhi = g_Whi + ((size_t)e * H + bn + crow) * H + s0 * 8;
    const __half* pBlo = g_Wlo + ((size_t)e * H + bn + crow) * H + s0 * 8;

#define ISSUE_STAGE(stg, kc) do { \
        uint32_t db = sbase + (stg) * STAGE_B; \
        int ko = (kc) * BK; \
        cpasync16(db + d0,               pAhi + ko); \
        cpasync16(db + d1,               pAhi + ko + 8); \
        cpasync16(db + PLANE_B + d0,     pBhi + ko); \
        cpasync16(db + PLANE_B + d1,     pBhi + ko + 8); \
        cpasync16(db + 2*PLANE_B + d0,   pBlo + ko); \
        cpasync16(db + 2*PLANE_B + d1,   pBlo + ko + 8); \
        asm volatile("cp.async.commit_group;" ::: "memory"); \
    } while (0)

    float D[2][4][4];
#pragma unroll
    for (int mt = 0; mt < 2; mt++)
#pragma unroll
        for (int nt = 0; nt < 4; nt++)
#pragma unroll
            for (int r = 0; r < 4; r++) D[mt][nt][r] = 0.f;

    const int mrow = (wid >> 2) * 32 + (lane & 15);   // + mt*16
    const int nrow = (wid & 3) * 32 + (lane & 15);    // + np*16
    const int chalf = lane >> 4;                      // 16B half within k16

    ISSUE_STAGE(0, 0);
    ISSUE_STAGE(1, 1);
    ISSUE_STAGE(2, 2);
    ISSUE_STAGE(3, 3);

    for (int kc = 0; kc < KITER; kc++) {
        if (kc < KITER - 3)       asm volatile("cp.async.wait_group 3;" ::: "memory");
        else if (kc == KITER - 3) asm volatile("cp.async.wait_group 2;" ::: "memory");
        else if (kc == KITER - 2) asm volatile("cp.async.wait_group 1;" ::: "memory");
        else                      asm volatile("cp.async.wait_group 0;" ::: "memory");
        __syncthreads();

        const uint32_t ab = sbase + (kc % NSTAGE) * STAGE_B;
#pragma unroll
        for (int ks = 0; ks < 4; ks++) {
            const int seg = ks * 2 + chalf;
            uint32_t ahi[2][4], bh[2][4], bl[2][4];
#pragma unroll
            for (int mt = 0; mt < 2; mt++) {
                int r = mrow + mt * 16;
                uint32_t ad = ab + r * ROW_B + ((seg ^ (r & 7)) * 16);
                ldsm4(ahi[mt][0], ahi[mt][1], ahi[mt][2], ahi[mt][3], ad);
            }
#pragma unroll
            for (int np = 0; np < 2; np++) {
                int r = nrow + np * 16;
                uint32_t bd = ab + PLANE_B + r * ROW_B + ((seg ^ (r & 7)) * 16);
                ldsm4(bh[np][0], bh[np][1], bh[np][2], bh[np][3], bd);
                ldsm4(bl[np][0], bl[np][1], bl[np][2], bl[np][3], bd + PLANE_B);
            }
#pragma unroll
            for (int t = 0; t < 2; t++)
#pragma unroll
                for (int mt = 0; mt < 2; mt++)
#pragma unroll
                    for (int nt = 0; nt < 4; nt++) {
                        int np = nt >> 1, od = nt & 1;
                        if (t == 0)
                            mma16816(D[mt][nt], ahi[mt], bh[np][od], bh[np][2 + od]);
                        else
                            mma16816(D[mt][nt], ahi[mt], bl[np][od], bl[np][2 + od]);
                    }
        }
        __syncthreads();   // all warps done reading stage kc%4
        if (kc + 4 < KITER) ISSUE_STAGE(kc % NSTAGE, kc + 4);
    }

    // ---- epilogue: gate * (D/64 + bias) scattered to token rows ----
    const int wm = (wid >> 2) * 32;
    const int wn = (wid & 3) * 32;
#pragma unroll
    for (int mt = 0; mt < 2; mt++) {
#pragma unroll
        for (int half = 0; half < 2; half++) {
            int r = wm + mt * 16 + (lane >> 2) + half * 8;
            int tok = s_tok[r];
            if (tok < 0) continue;
            float g = g_gate[tok];
            float* orow = out + (size_t)tok * H + bn + wn;
#pragma unroll
            for (int nt = 0; nt < 4; nt++) {
                int c = nt * 8 + (lane & 3) * 2;
                float2 bb = *(const float2*)(bias + (size_t)e * H + bn + wn + c);
                float2 v;
                v.x = g * (D[mt][nt][half * 2 + 0] * INV_WSCALE + bb.x);
                v.y = g * (D[mt][nt][half * 2 + 1] * INV_WSCALE + bb.y);
                *(float2*)(orow + c) = v;
            }
        }
    }
}

extern "C" void kernel_launch(void* const* d_in, const int* in_sizes, int n_in,
                              void* d_out, int out_size) {
    const float* x  = (const float*)d_in[0];   // [T, H]
    const float* wg = (const float*)d_in[1];   // [H, E]
    const float* W  = (const float*)d_in[2];   // [E, H, H]
    const float* b  = (const float*)d_in[3];   // [E, H]
    float* out = (float*)d_out;                // [T, H]

    cudaFuncSetAttribute(moe_gemm, cudaFuncAttributeMaxDynamicSharedMemorySize, GEMM_SMEM);

    route_kernel<<<T_TOK / 8, 256>>>(x, wg);
    scan_kernel<<<1, 1024>>>();
    conv_kernel<<<24576, 128>>>(W, x, out);
    dim3 grid(H / BN, T_TOK / BM);             // (8, 64)
    moe_gemm<<<grid, 512, GEMM_SMEM>>>(b, out);
}

// round 11
// speedup vs baseline: 1.3481x; 1.0364x over previous
#include <cuda_runtime.h>
#include <cuda_fp16.h>
#include <math.h>
#include <stdint.h>

#define T_TOK 8192
#define H 1024
#define E 8
#define CAP 1024   // capacity = T/E
#define WSCALE 64.0f
#define INV_WSCALE (1.0f / 64.0f)

// ---------------- scratch (no allocations allowed) ----------------
__device__ int   g_expert_idx[T_TOK];
__device__ float g_gate[T_TOK];
__device__ int   g_slot_token[E * CAP];   // token id per (expert, slot), -1 if empty
__device__ unsigned char g_dropped[T_TOK];
__device__ __align__(256) __half g_Whi[E * H * H];   // 16 MB (fp16 of 64*W)
__device__ __align__(256) __half g_Wlo[E * H * H];   // 16 MB (residual)
__device__ __align__(256) __half g_Ahi[T_TOK * H];   // 16 MB (gathered per-slot x, fp16)

// ---------------- kernel 1: routing ----------------
__global__ void route_kernel(const float* __restrict__ x,
                             const float* __restrict__ wg) {
    __shared__ float s_wg[H * E];
    for (int i = threadIdx.x; i < H * E; i += blockDim.x) s_wg[i] = wg[i];
    __syncthreads();

    int warp = (blockIdx.x * blockDim.x + threadIdx.x) >> 5;
    int lane = threadIdx.x & 31;
    if (warp >= T_TOK) return;

    const float* xp = x + (size_t)warp * H;
    float acc[E];
#pragma unroll
    for (int e = 0; e < E; e++) acc[e] = 0.f;
    for (int k = lane; k < H; k += 32) {
        float xv = xp[k];
        const float* w = s_wg + k * E;
#pragma unroll
        for (int e = 0; e < E; e++) acc[e] = fmaf(xv, w[e], acc[e]);
    }
#pragma unroll
    for (int e = 0; e < E; e++) {
#pragma unroll
        for (int o = 16; o > 0; o >>= 1)
            acc[e] += __shfl_down_sync(0xffffffffu, acc[e], o);
    }
    if (lane == 0) {
        float m = acc[0]; int bi = 0;
#pragma unroll
        for (int e = 1; e < E; e++)
            if (acc[e] > m) { m = acc[e]; bi = e; }
        float s = 0.f;
#pragma unroll
        for (int e = 0; e < E; e++) s += expf(acc[e] - m);
        g_expert_idx[warp] = bi;
        g_gate[warp]       = 1.f / s;
    }
}

// ---------------- kernel 2: order-preserving scan (warp-shuffle) ----------------
__global__ void scan_kernel() {
    __shared__ unsigned long long w0[32], w1[32];
    const int tid = threadIdx.x;
    const int lane = tid & 31, wid = tid >> 5;

    const int base = tid * 8;
    int eidx[8];
    unsigned long long c0 = 0ULL, c1 = 0ULL;
#pragma unroll
    for (int j = 0; j < 8; j++) {
        int e = g_expert_idx[base + j];
        eidx[j] = e;
        if (e < 4) c0 += 1ULL << (16 * e);
        else       c1 += 1ULL << (16 * (e - 4));
    }
    unsigned long long s0 = c0, s1 = c1;
#pragma unroll
    for (int d = 1; d < 32; d <<= 1) {
        unsigned long long t0 = __shfl_up_sync(0xffffffffu, s0, d);
        unsigned long long t1 = __shfl_up_sync(0xffffffffu, s1, d);
        if (lane >= d) { s0 += t0; s1 += t1; }
    }
    if (lane == 31) { w0[wid] = s0; w1[wid] = s1; }

    for (int i = tid; i < E * CAP; i += 1024) g_slot_token[i] = -1;
    __syncthreads();
    if (wid == 0) {
        unsigned long long v0 = w0[lane], v1 = w1[lane];
#pragma unroll
        for (int d = 1; d < 32; d <<= 1) {
            unsigned long long t0 = __shfl_up_sync(0xffffffffu, v0, d);
            unsigned long long t1 = __shfl_up_sync(0xffffffffu, v1, d);
            if (lane >= d) { v0 += t0; v1 += t1; }
        }
        w0[lane] = v0; w1[lane] = v1;
    }
    __syncthreads();
    unsigned long long o0 = s0 - c0 + (wid > 0 ? w0[wid - 1] : 0ULL);
    unsigned long long o1 = s1 - c1 + (wid > 0 ? w1[wid - 1] : 0ULL);

    int off[E];
#pragma unroll
    for (int e = 0; e < 4; e++) {
        off[e]     = (int)((o0 >> (16 * e)) & 0xFFFFULL);
        off[e + 4] = (int)((o1 >> (16 * e)) & 0xFFFFULL);
    }
#pragma unroll
    for (int j = 0; j < 8; j++) {
        int t = base + j;
        int e = eidx[j];
        int p = 0;
#pragma unroll
        for (int q = 0; q < E; q++)
            if (e == q) { p = off[q]; off[q] = p + 1; }
        if (p < CAP) { g_slot_token[e * CAP + p] = t; g_dropped[t] = 0; }
        else         { g_dropped[t] = 1; }
    }
}

// ---------------- kernel 3: fused convert (MLP=4) + zero dropped ----------------
// blocks [0,2048): W (16 elems/thread); [2048,4096): A rows; [4096,12288): zero dropped
__global__ void conv_kernel(const float* __restrict__ W, const float* __restrict__ x,
                            float* __restrict__ out) {
    int bid = blockIdx.x;
    int tid = threadIdx.x;
    if (bid < 2048) {
        size_t base = ((size_t)bid * 256 + tid) * 16;
        float4 a0 = *(const float4*)(W + base);
        float4 a1 = *(const float4*)(W + base + 4);
        float4 a2 = *(const float4*)(W + base + 8);
        float4 a3 = *(const float4*)(W + base + 12);
        float v[16] = {a0.x,a0.y,a0.z,a0.w, a1.x,a1.y,a1.z,a1.w,
                       a2.x,a2.y,a2.z,a2.w, a3.x,a3.y,a3.z,a3.w};
        __half hi[16], lo[16];
#pragma unroll
        for (int i = 0; i < 16; i++) {
            float s = v[i] * WSCALE;
            hi[i] = __float2half_rn(s);
            lo[i] = __float2half_rn(s - __half2float(hi[i]));
        }
        *(uint4*)(g_Whi + base)     = ((uint4*)hi)[0];
        *(uint4*)(g_Whi + base + 8) = ((uint4*)hi)[1];
        *(uint4*)(g_Wlo + base)     = ((uint4*)lo)[0];
        *(uint4*)(g_Wlo + base + 8) = ((uint4*)lo)[1];
    } else if (bid < 4096) {
        size_t gbase = ((size_t)(bid - 2048) * 256 + tid) * 16;
        int r   = (int)(gbase >> 10);
        int col = (int)(gbase & 1023);
        int tok = g_slot_token[r];
        if (tok < 0) {
            *(uint4*)(g_Ahi + gbase)     = make_uint4(0, 0, 0, 0);
            *(uint4*)(g_Ahi + gbase + 8) = make_uint4(0, 0, 0, 0);
            return;
        }
        const float* xr = x + (size_t)tok * H + col;
        float4 a0 = *(const float4*)(xr);
        float4 a1 = *(const float4*)(xr + 4);
        float4 a2 = *(const float4*)(xr + 8);
        float4 a3 = *(const float4*)(xr + 12);
        float v[16] = {a0.x,a0.y,a0.z,a0.w, a1.x,a1.y,a1.z,a1.w,
                       a2.x,a2.y,a2.z,a2.w, a3.x,a3.y,a3.z,a3.w};
        __half h[16];
#pragma unroll
        for (int i = 0; i < 16; i++) h[i] = __float2half_rn(v[i]);
        *(uint4*)(g_Ahi + gbase)     = ((uint4*)h)[0];
        *(uint4*)(g_Ahi + gbase + 8) = ((uint4*)h)[1];
    } else {
        int t = bid - 4096;
        if (!g_dropped[t]) return;
        float4* row = (float4*)(out + (size_t)t * H);
        row[tid] = make_float4(0.f, 0.f, 0.f, 0.f);
    }
}

// ---------------- kernel 4: GEMM, fp16 2-term, single-barrier 4-stage pipeline ----------------
#define BM 128
#define BN 128
#define BK 64                      // fp16 per chunk = 128B rows
#define KITER (H / BK)             // 16
#define ROW_B 128                  // bytes per smem row
#define PLANE_B (BM * ROW_B)       // 16384
#define STAGE_B (3 * PLANE_B)      // 49152
#define NSTAGE 4
#define SMEM_TOK 512
#define GEMM_SMEM (SMEM_TOK + NSTAGE * STAGE_B)   // 197120

__device__ __forceinline__ uint32_t smem_u32(const void* p) {
    uint32_t a;
    asm("{ .reg .u64 t; cvta.to.shared.u64 t, %1; cvt.u32.u64 %0, t; }" : "=r"(a) : "l"(p));
    return a;
}
__device__ __forceinline__ void cpasync16(uint32_t dst, const void* src) {
    asm volatile("cp.async.cg.shared.global [%0], [%1], 16;" :: "r"(dst), "l"(src));
}
__device__ __forceinline__ void ldsm4(uint32_t& r0, uint32_t& r1, uint32_t& r2, uint32_t& r3,
                                      uint32_t addr) {
    asm volatile("ldmatrix.sync.aligned.m8n8.x4.shared.b16 {%0,%1,%2,%3}, [%4];"
                 : "=r"(r0), "=r"(r1), "=r"(r2), "=r"(r3) : "r"(addr));
}
__device__ __forceinline__ void mma16816(float* d, const uint32_t* a, uint32_t b0, uint32_t b1) {
    asm volatile("mma.sync.aligned.m16n8k16.row.col.f32.f16.f16.f32 "
                 "{%0,%1,%2,%3}, {%4,%5,%6,%7}, {%8,%9}, {%0,%1,%2,%3};"
                 : "+f"(d[0]), "+f"(d[1]), "+f"(d[2]), "+f"(d[3])
                 : "r"(a[0]), "r"(a[1]), "r"(a[2]), "r"(a[3]), "r"(b0), "r"(b1));
}

__global__ void __launch_bounds__(512, 1)
moe_gemm(const float* __restrict__ bias, float* __restrict__ out) {
    extern __shared__ char smem[];
    int* s_tok = (int*)smem;
    const uint32_t sbase = smem_u32(smem) + SMEM_TOK;

    const int tid  = threadIdx.x;
    const int lane = tid & 31;
    const int wid  = tid >> 5;             // 0..15, warp grid 4(M) x 4(N)
    const int bm = blockIdx.y * BM;
    const int bn = blockIdx.x * BN;
    const int e  = bm >> 10;

    if (tid < BM) s_tok[tid] = g_slot_token[bm + tid];

    // ---- cp.async mapping: row = tid>>2 (4 thr/row), 2 x 16B segs each ----
    const int crow = tid >> 2;
    const int s0   = (tid & 3) * 2;
    const uint32_t d0 = (uint32_t)(crow * ROW_B + ((s0     ^ (crow & 7)) * 16));
    const uint32_t d1 = (uint32_t)(crow * ROW_B + (((s0+1) ^ (crow & 7)) * 16));
    const __half* pAhi = g_Ahi + (size_t)(bm + crow) * H + s0 * 8;
    const __half* pBhi = g_Whi + ((size_t)e * H + bn + crow) * H + s0 * 8;
    const __half* pBlo = g_Wlo + ((size_t)e * H + bn + crow) * H + s0 * 8;

#define ISSUE_STAGE(stg, kc) do { \
        uint32_t db = sbase + (stg) * STAGE_B; \
        int ko = (kc) * BK; \
        cpasync16(db + d0,               pAhi + ko); \
        cpasync16(db + d1,               pAhi + ko + 8); \
        cpasync16(db + PLANE_B + d0,     pBhi + ko); \
        cpasync16(db + PLANE_B + d1,     pBhi + ko + 8); \
        cpasync16(db + 2*PLANE_B + d0,   pBlo + ko); \
        cpasync16(db + 2*PLANE_B + d1,   pBlo + ko + 8); \
        asm volatile("cp.async.commit_group;" ::: "memory"); \
    } while (0)

    float D[2][4][4];
#pragma unroll
    for (int mt = 0; mt < 2; mt++)
#pragma unroll
        for (int nt = 0; nt < 4; nt++)
#pragma unroll
            for (int r = 0; r < 4; r++) D[mt][nt][r] = 0.f;

    const int mrow = (wid >> 2) * 32 + (lane & 15);   // + mt*16
    const int nrow = (wid & 3) * 32 + (lane & 15);    // + np*16
    const int chalf = lane >> 4;                      // 16B half within k16

    // prologue: 3 of 4 stages in flight
    ISSUE_STAGE(0, 0);
    ISSUE_STAGE(1, 1);
    ISSUE_STAGE(2, 2);

#pragma unroll 1
    for (int kb = 0; kb < KITER; kb += NSTAGE) {
#pragma unroll
        for (int s = 0; s < NSTAGE; s++) {
            const int kc = kb + s;
            // wait until chunk kc is resident (pending = chunks issued after kc)
            if (kc < KITER - 2)       asm volatile("cp.async.wait_group 2;" ::: "memory");
            else if (kc == KITER - 2) asm volatile("cp.async.wait_group 1;" ::: "memory");
            else                      asm volatile("cp.async.wait_group 0;" ::: "memory");
            __syncthreads();   // single barrier: proves all warps finished stage (s+3)&3 reads

            // issue-early into the stage read LAST iteration (safe past the barrier)
            if (kc + 3 < KITER) ISSUE_STAGE((s + 3) & 3, kc + 3);

            const uint32_t ab = sbase + s * STAGE_B;   // compile-time stage offset
#pragma unroll
            for (int ks = 0; ks < 4; ks++) {
                const int seg = ks * 2 + chalf;
                uint32_t ahi[2][4], bh[2][4], bl[2][4];
#pragma unroll
                for (int mt = 0; mt < 2; mt++) {
                    int r = mrow + mt * 16;
                    uint32_t ad = ab + r * ROW_B + ((seg ^ (r & 7)) * 16);
                    ldsm4(ahi[mt][0], ahi[mt][1], ahi[mt][2], ahi[mt][3], ad);
                }
#pragma unroll
                for (int np = 0; np < 2; np++) {
                    int r = nrow + np * 16;
                    uint32_t bd = ab + PLANE_B + r * ROW_B + ((seg ^ (r & 7)) * 16);
                    ldsm4(bh[np][0], bh[np][1], bh[np][2], bh[np][3], bd);
                    ldsm4(bl[np][0], bl[np][1], bl[np][2], bl[np][3], bd + PLANE_B);
                }
#pragma unroll
                for (int t = 0; t < 2; t++)
#pragma unroll
                    for (int mt = 0; mt < 2; mt++)
#pragma unroll
                        for (int nt = 0; nt < 4; nt++) {
                            int np = nt >> 1, od = nt & 1;
                            if (t == 0)
                                mma16816(D[mt][nt], ahi[mt], bh[np][od], bh[np][2 + od]);
                            else
                                mma16816(D[mt][nt], ahi[mt], bl[np][od], bl[np][2 + od]);
                        }
            }
        }
    }

    // ---- epilogue: gate * (D/64 + bias) scattered to token rows ----
    const int wm = (wid >> 2) * 32;
    const int wn = (wid & 3) * 32;
#pragma unroll
    for (int mt = 0; mt < 2; mt++) {
#pragma unroll
        for (int half = 0; half < 2; half++) {
            int r = wm + mt * 16 + (lane >> 2) + half * 8;
            int tok = s_tok[r];
            if (tok < 0) continue;
            float g = g_gate[tok];
            float* orow = out + (size_t)tok * H + bn + wn;
#pragma unroll
            for (int nt = 0; nt < 4; nt++) {
                int c = nt * 8 + (lane & 3) * 2;
                float2 bb = *(const float2*)(bias + (size_t)e * H + bn + wn + c);
                float2 v;
                v.x = g * (D[mt][nt][half * 2 + 0] * INV_WSCALE + bb.x);
                v.y = g * (D[mt][nt][half * 2 + 1] * INV_WSCALE + bb.y);
                *(float2*)(orow + c) = v;
            }
        }
    }
}

extern "C" void kernel_launch(void* const* d_in, const int* in_sizes, int n_in,
                              void* d_out, int out_size) {
    const float* x  = (const float*)d_in[0];   // [T, H]
    const float* wg = (const float*)d_in[1];   // [H, E]
    const float* W  = (const float*)d_in[2];   // [E, H, H]
    const float* b  = (const float*)d_in[3];   // [E, H]
    float* out = (float*)d_out;                // [T, H]

    cudaFuncSetAttribute(moe_gemm, cudaFuncAttributeMaxDynamicSharedMemorySize, GEMM_SMEM);

    route_kernel<<<T_TOK / 8, 256>>>(x, wg);
    scan_kernel<<<1, 1024>>>();
    conv_kernel<<<12288, 256>>>(W, x, out);
    dim3 grid(H / BN, T_TOK / BM);             // (8, 64)
    moe_gemm<<<grid, 512, GEMM_SMEM>>>(b, out);
}

// round 12
// speedup vs baseline: 1.3967x; 1.0360x over previous
#include <cuda_runtime.h>
#include <cuda_fp16.h>
#include <math.h>
#include <stdint.h>

#define T_TOK 8192
#define H 1024
#define E 8
#define CAP 1024   // capacity = T/E
#define WSCALE 64.0f
#define INV_WSCALE (1.0f / 64.0f)

// ---------------- scratch (no allocations allowed) ----------------
__device__ int   g_expert_idx[T_TOK];
__device__ float g_gate[T_TOK];
__device__ int   g_slot_token[E * CAP];   // token id per (expert, slot), -1 if empty
__device__ unsigned char g_dropped[T_TOK];
__device__ __align__(256) __half g_Whi[E * H * H];   // 16 MB (fp16 of 64*W)
__device__ __align__(256) __half g_Wlo[E * H * H];   // 16 MB (residual)
__device__ __align__(256) __half g_xh[T_TOK * H];    // 16 MB (fp16 x, token order)

// ---------------- kernel 1: routing + fp16 conversion of x ----------------
__global__ void route_kernel(const float* __restrict__ x,
                             const float* __restrict__ wg) {
    __shared__ float s_wg[H * E];
    for (int i = threadIdx.x; i < H * E; i += blockDim.x) s_wg[i] = wg[i];
    __syncthreads();

    int warp = (blockIdx.x * blockDim.x + threadIdx.x) >> 5;
    int lane = threadIdx.x & 31;
    if (warp >= T_TOK) return;

    const float* xp = x + (size_t)warp * H;
    __half* xh = g_xh + (size_t)warp * H;
    float acc[E];
#pragma unroll
    for (int e = 0; e < E; e++) acc[e] = 0.f;
    for (int k = lane; k < H; k += 32) {
        float xv = xp[k];
        xh[k] = __float2half_rn(xv);          // emit fp16 copy (A-conv fused here)
        const float* w = s_wg + k * E;
#pragma unroll
        for (int e = 0; e < E; e++) acc[e] = fmaf(xv, w[e], acc[e]);
    }
#pragma unroll
    for (int e = 0; e < E; e++) {
#pragma unroll
        for (int o = 16; o > 0; o >>= 1)
            acc[e] += __shfl_down_sync(0xffffffffu, acc[e], o);
    }
    if (lane == 0) {
        float m = acc[0]; int bi = 0;
#pragma unroll
        for (int e = 1; e < E; e++)
            if (acc[e] > m) { m = acc[e]; bi = e; }
        float s = 0.f;
#pragma unroll
        for (int e = 0; e < E; e++) s += expf(acc[e] - m);
        g_expert_idx[warp] = bi;
        g_gate[warp]       = 1.f / s;
    }
}

// ---------------- kernel 2: order-preserving scan (warp-shuffle) ----------------
__global__ void scan_kernel() {
    __shared__ unsigned long long w0[32], w1[32];
    const int tid = threadIdx.x;
    const int lane = tid & 31, wid = tid >> 5;

    const int base = tid * 8;
    int eidx[8];
    unsigned long long c0 = 0ULL, c1 = 0ULL;
#pragma unroll
    for (int j = 0; j < 8; j++) {
        int e = g_expert_idx[base + j];
        eidx[j] = e;
        if (e < 4) c0 += 1ULL << (16 * e);
        else       c1 += 1ULL << (16 * (e - 4));
    }
    unsigned long long s0 = c0, s1 = c1;
#pragma unroll
    for (int d = 1; d < 32; d <<= 1) {
        unsigned long long t0 = __shfl_up_sync(0xffffffffu, s0, d);
        unsigned long long t1 = __shfl_up_sync(0xffffffffu, s1, d);
        if (lane >= d) { s0 += t0; s1 += t1; }
    }
    if (lane == 31) { w0[wid] = s0; w1[wid] = s1; }

    for (int i = tid; i < E * CAP; i += 1024) g_slot_token[i] = -1;
    __syncthreads();
    if (wid == 0) {
        unsigned long long v0 = w0[lane], v1 = w1[lane];
#pragma unroll
        for (int d = 1; d < 32; d <<= 1) {
            unsigned long long t0 = __shfl_up_sync(0xffffffffu, v0, d);
            unsigned long long t1 = __shfl_up_sync(0xffffffffu, v1, d);
            if (lane >= d) { v0 += t0; v1 += t1; }
        }
        w0[lane] = v0; w1[lane] = v1;
    }
    __syncthreads();
    unsigned long long o0 = s0 - c0 + (wid > 0 ? w0[wid - 1] : 0ULL);
    unsigned long long o1 = s1 - c1 + (wid > 0 ? w1[wid - 1] : 0ULL);

    int off[E];
#pragma unroll
    for (int e = 0; e < 4; e++) {
        off[e]     = (int)((o0 >> (16 * e)) & 0xFFFFULL);
        off[e + 4] = (int)((o1 >> (16 * e)) & 0xFFFFULL);
    }
#pragma unroll
    for (int j = 0; j < 8; j++) {
        int t = base + j;
        int e = eidx[j];
        int p = 0;
#pragma unroll
        for (int q = 0; q < E; q++)
            if (e == q) { p = off[q]; off[q] = p + 1; }
        if (p < CAP) { g_slot_token[e * CAP + p] = t; g_dropped[t] = 0; }
        else         { g_dropped[t] = 1; }
    }
}

// ---------------- kernel 3: convert W (hi/lo fp16 of 64*W) + zero dropped rows ----------------
// blocks [0, 2048): W (16 elems/thread, 256 thr); [2048, 10240): dropped-token zeroing
__global__ void convW_kernel(const float* __restrict__ W, float* __restrict__ out) {
    int bid = blockIdx.x;
    int tid = threadIdx.x;
    if (bid < 2048) {
        size_t base = ((size_t)bid * 256 + tid) * 16;
        float4 a0 = *(const float4*)(W + base);
        float4 a1 = *(const float4*)(W + base + 4);
        float4 a2 = *(const float4*)(W + base + 8);
        float4 a3 = *(const float4*)(W + base + 12);
        float v[16] = {a0.x,a0.y,a0.z,a0.w, a1.x,a1.y,a1.z,a1.w,
                       a2.x,a2.y,a2.z,a2.w, a3.x,a3.y,a3.z,a3.w};
        __half hi[16], lo[16];
#pragma unroll
        for (int i = 0; i < 16; i++) {
            float s = v[i] * WSCALE;
            hi[i] = __float2half_rn(s);
            lo[i] = __float2half_rn(s - __half2float(hi[i]));
        }
        *(uint4*)(g_Whi + base)     = ((uint4*)hi)[0];
        *(uint4*)(g_Whi + base + 8) = ((uint4*)hi)[1];
        *(uint4*)(g_Wlo + base)     = ((uint4*)lo)[0];
        *(uint4*)(g_Wlo + base + 8) = ((uint4*)lo)[1];
    } else {
        int t = bid - 2048;
        if (!g_dropped[t]) return;
        float4* row = (float4*)(out + (size_t)t * H);
        row[tid] = make_float4(0.f, 0.f, 0.f, 0.f);
    }
}

// ---------------- kernel 4: GEMM, fp16 2-term, gathered A, frag double-buffer ----------------
#define BM 128
#define BN 128
#define BK 64                      // fp16 per chunk = 128B rows
#define KITER (H / BK)             // 16
#define ROW_B 128                  // bytes per smem row
#define PLANE_B (BM * ROW_B)       // 16384
#define STAGE_B (3 * PLANE_B)      // 49152
#define NSTAGE 4
#define SMEM_TOK 512
#define GEMM_SMEM (SMEM_TOK + NSTAGE * STAGE_B)   // 197120

__device__ __forceinline__ uint32_t smem_u32(const void* p) {
    uint32_t a;
    asm("{ .reg .u64 t; cvta.to.shared.u64 t, %1; cvt.u32.u64 %0, t; }" : "=r"(a) : "l"(p));
    return a;
}
__device__ __forceinline__ void cpasync16(uint32_t dst, const void* src) {
    asm volatile("cp.async.cg.shared.global [%0], [%1], 16;" :: "r"(dst), "l"(src));
}
__device__ __forceinline__ void cpasync16z(uint32_t dst, const void* src, uint32_t sz) {
    asm volatile("cp.async.cg.shared.global [%0], [%1], 16, %2;" :: "r"(dst), "l"(src), "r"(sz));
}
__device__ __forceinline__ void ldsm4(uint32_t& r0, uint32_t& r1, uint32_t& r2, uint32_t& r3,
                                      uint32_t addr) {
    asm volatile("ldmatrix.sync.aligned.m8n8.x4.shared.b16 {%0,%1,%2,%3}, [%4];"
                 : "=r"(r0), "=r"(r1), "=r"(r2), "=r"(r3) : "r"(addr));
}
__device__ __forceinline__ void mma16816(float* d, const uint32_t* a, uint32_t b0, uint32_t b1) {
    asm volatile("mma.sync.aligned.m16n8k16.row.col.f32.f16.f16.f32 "
                 "{%0,%1,%2,%3}, {%4,%5,%6,%7}, {%8,%9}, {%0,%1,%2,%3};"
                 : "+f"(d[0]), "+f"(d[1]), "+f"(d[2]), "+f"(d[3])
                 : "r"(a[0]), "r"(a[1]), "r"(a[2]), "r"(a[3]), "r"(b0), "r"(b1));
}

__global__ void __launch_bounds__(512, 1)
moe_gemm(const float* __restrict__ bias, float* __restrict__ out) {
    extern __shared__ char smem[];
    int* s_tok = (int*)smem;
    const uint32_t sbase = smem_u32(smem) + SMEM_TOK;

    const int tid  = threadIdx.x;
    const int lane = tid & 31;
    const int wid  = tid >> 5;             // 0..15, warp grid 4(M) x 4(N)
    const int bm = blockIdx.y * BM;
    const int bn = blockIdx.x * BN;
    const int e  = bm >> 10;

    if (tid < BM) s_tok[tid] = g_slot_token[bm + tid];

    // ---- cp.async mapping: row = tid>>2 (4 thr/row), 2 x 16B segs each ----
    const int crow = tid >> 2;
    const int s0   = (tid & 3) * 2;
    const uint32_t d0 = (uint32_t)(crow * ROW_B + ((s0     ^ (crow & 7)) * 16));
    const uint32_t d1 = (uint32_t)(crow * ROW_B + (((s0+1) ^ (crow & 7)) * 16));
    // A is gathered straight from g_xh by token id; empty slot -> zero-fill copy
    const int atok = g_slot_token[bm + crow];
    const uint32_t asz = (atok >= 0) ? 16u : 0u;
    const __half* pA   = g_xh + (size_t)(atok >= 0 ? atok : 0) * H + s0 * 8;
    const __half* pBhi = g_Whi + ((size_t)e * H + bn + crow) * H + s0 * 8;
    const __half* pBlo = g_Wlo + ((size_t)e * H + bn + crow) * H + s0 * 8;

#define ISSUE_STAGE(stg, kc) do { \
        uint32_t db = sbase + (stg) * STAGE_B; \
        int ko = (kc) * BK; \
        cpasync16z(db + d0,              pA   + ko,     asz); \
        cpasync16z(db + d1,              pA   + ko + 8, asz); \
        cpasync16(db + PLANE_B + d0,     pBhi + ko); \
        cpasync16(db + PLANE_B + d1,     pBhi + ko + 8); \
        cpasync16(db + 2*PLANE_B + d0,   pBlo + ko); \
        cpasync16(db + 2*PLANE_B + d1,   pBlo + ko + 8); \
        asm volatile("cp.async.commit_group;" ::: "memory"); \
    } while (0)

    float D[2][4][4];
#pragma unroll
    for (int mt = 0; mt < 2; mt++)
#pragma unroll
        for (int nt = 0; nt < 4; nt++)
#pragma unroll
            for (int r = 0; r < 4; r++) D[mt][nt][r] = 0.f;

    const int mrow = (wid >> 2) * 32 + (lane & 15);   // + mt*16
    const int nrow = (wid & 3) * 32 + (lane & 15);    // + np*16
    const int chalf = lane >> 4;                      // 16B half within k16

    // hoisted swizzled ldsm offsets (stage-relative), indexed by compile-time ks
    uint32_t swzA[2][4], swzB[2][4];
#pragma unroll
    for (int mt = 0; mt < 2; mt++) {
        int r = mrow + mt * 16;
#pragma unroll
        for (int ks = 0; ks < 4; ks++)
            swzA[mt][ks] = (uint32_t)(r * ROW_B + (((ks * 2 + chalf) ^ (r & 7)) << 4));
    }
#pragma unroll
    for (int np = 0; np < 2; np++) {
        int r = nrow + np * 16;
#pragma unroll
        for (int ks = 0; ks < 4; ks++)
            swzB[np][ks] = (uint32_t)(PLANE_B + r * ROW_B + (((ks * 2 + chalf) ^ (r & 7)) << 4));
    }

#define LOAD_FRAGS(ks_, b_) do { \
        ldsm4(fa[b_][0][0], fa[b_][0][1], fa[b_][0][2], fa[b_][0][3], ab + swzA[0][ks_]); \
        ldsm4(fa[b_][1][0], fa[b_][1][1], fa[b_][1][2], fa[b_][1][3], ab + swzA[1][ks_]); \
        ldsm4(fbh[b_][0][0], fbh[b_][0][1], fbh[b_][0][2], fbh[b_][0][3], ab + swzB[0][ks_]); \
        ldsm4(fbl[b_][0][0], fbl[b_][0][1], fbl[b_][0][2], fbl[b_][0][3], ab + swzB[0][ks_] + PLANE_B); \
        ldsm4(fbh[b_][1][0], fbh[b_][1][1], fbh[b_][1][2], fbh[b_][1][3], ab + swzB[1][ks_]); \
        ldsm4(fbl[b_][1][0], fbl[b_][1][1], fbl[b_][1][2], fbl[b_][1][3], ab + swzB[1][ks_] + PLANE_B); \
    } while (0)

    // prologue: 3 of 4 stages in flight
    ISSUE_STAGE(0, 0);
    ISSUE_STAGE(1, 1);
    ISSUE_STAGE(2, 2);

#pragma unroll 1
    for (int kb = 0; kb < KITER; kb += NSTAGE) {
#pragma unroll
        for (int s = 0; s < NSTAGE; s++) {
            const int kc = kb + s;
            if (kc < KITER - 2)       asm volatile("cp.async.wait_group 2;" ::: "memory");
            else if (kc == KITER - 2) asm volatile("cp.async.wait_group 1;" ::: "memory");
            else                      asm volatile("cp.async.wait_group 0;" ::: "memory");
            __syncthreads();   // proves all warps finished stage (s+3)&3 reads

            if (kc + 3 < KITER) ISSUE_STAGE((s + 3) & 3, kc + 3);

            const uint32_t ab = sbase + s * STAGE_B;   // compile-time stage offset
            uint32_t fa[2][2][4], fbh[2][2][4], fbl[2][2][4];
            LOAD_FRAGS(0, 0);
#pragma unroll
            for (int ks = 0; ks < 4; ks++) {
                const int cur = ks & 1;
                if (ks < 3) {
                    const int nxt = cur ^ 1;
                    if (ks == 0)      LOAD_FRAGS(1, 1);
                    else if (ks == 1) LOAD_FRAGS(2, 0);
                    else              LOAD_FRAGS(3, 1);
                    (void)nxt;
                }
#pragma unroll
                for (int t = 0; t < 2; t++)
#pragma unroll
                    for (int mt = 0; mt < 2; mt++)
#pragma unroll
                        for (int nt = 0; nt < 4; nt++) {
                            int np = nt >> 1, od = nt & 1;
                            if (t == 0)
                                mma16816(D[mt][nt], fa[cur][mt], fbh[cur][np][od], fbh[cur][np][2 + od]);
                            else
                                mma16816(D[mt][nt], fa[cur][mt], fbl[cur][np][od], fbl[cur][np][2 + od]);
                        }
            }
        }
    }

    // ---- epilogue: gate * (D/64 + bias) scattered to token rows ----
    const int wm = (wid >> 2) * 32;
    const int wn = (wid & 3) * 32;
#pragma unroll
    for (int mt = 0; mt < 2; mt++) {
#pragma unroll
        for (int half = 0; half < 2; half++) {
            int r = wm + mt * 16 + (lane >> 2) + half * 8;
            int tok = s_tok[r];
            if (tok < 0) continue;
            float g = g_gate[tok];
            float* orow = out + (size_t)tok * H + bn + wn;
#pragma unroll
            for (int nt = 0; nt < 4; nt++) {
                int c = nt * 8 + (lane & 3) * 2;
                float2 bb = *(const float2*)(bias + (size_t)e * H + bn + wn + c);
                float2 v;
                v.x = g * (D[mt][nt][half * 2 + 0] * INV_WSCALE + bb.x);
                v.y = g * (D[mt][nt][half * 2 + 1] * INV_WSCALE + bb.y);
                *(float2*)(orow + c) = v;
            }
        }
    }
}

extern "C" void kernel_launch(void* const* d_in, const int* in_sizes, int n_in,
                              void* d_out, int out_size) {
    const float* x  = (const float*)d_in[0];   // [T, H]
    const float* wg = (const float*)d_in[1];   // [H, E]
    const float* W  = (const float*)d_in[2];   // [E, H, H]
    const float* b  = (const float*)d_in[3];   // [E, H]
    float* out = (float*)d_out;                // [T, H]

    cudaFuncSetAttribute(moe_gemm, cudaFuncAttributeMaxDynamicSharedMemorySize, GEMM_SMEM);

    route_kernel<<<T_TOK / 8, 256>>>(x, wg);
    scan_kernel<<<1, 1024>>>();
    convW_kernel<<<2048 + T_TOK, 256>>>(W, out);
    dim3 grid(H / BN, T_TOK / BM);             // (8, 64)
    moe_gemm<<<grid, 512, GEMM_SMEM>>>(b, out);
}

// round 14
// speedup vs baseline: 1.9340x; 1.3847x over previous
#include <cuda_runtime.h>
#include <cuda_fp16.h>
#include <math.h>
#include <stdint.h>

#define T_TOK 8192
#define H 1024
#define E 8
#define CAP 1024   // capacity = T/E

// ---------------- scratch (no allocations allowed) ----------------
__device__ int   g_expert_idx[T_TOK];
__device__ float g_gate[T_TOK];
__device__ int   g_slot_token[E * CAP];   // token id per (expert, slot), -1 if empty
__device__ unsigned char g_dropped[T_TOK];
__device__ __align__(256) __half g_Wh[E * H * H];    // 16 MB (fp16 W)
__device__ __align__(256) __half g_xh[T_TOK * H];    // 16 MB (fp16 x, token order)

// ---------------- kernel 1: routing + fp16 conversion of x ----------------
__global__ void route_kernel(const float* __restrict__ x,
                             const float* __restrict__ wg) {
    __shared__ float s_wg[H * E];
    for (int i = threadIdx.x; i < H * E; i += blockDim.x) s_wg[i] = wg[i];
    __syncthreads();

    int warp = (blockIdx.x * blockDim.x + threadIdx.x) >> 5;
    int lane = threadIdx.x & 31;
    if (warp >= T_TOK) return;

    const float* xp = x + (size_t)warp * H;
    __half* xh = g_xh + (size_t)warp * H;
    float acc[E];
#pragma unroll
    for (int e = 0; e < E; e++) acc[e] = 0.f;
    for (int k = lane; k < H; k += 32) {
        float xv = xp[k];
        xh[k] = __float2half_rn(xv);          // emit fp16 copy (A-conv fused)
        const float* w = s_wg + k * E;
#pragma unroll
        for (int e = 0; e < E; e++) acc[e] = fmaf(xv, w[e], acc[e]);
    }
#pragma unroll
    for (int e = 0; e < E; e++) {
#pragma unroll
        for (int o = 16; o > 0; o >>= 1)
            acc[e] += __shfl_down_sync(0xffffffffu, acc[e], o);
    }
    if (lane == 0) {
        float m = acc[0]; int bi = 0;
#pragma unroll
        for (int e = 1; e < E; e++)
            if (acc[e] > m) { m = acc[e]; bi = e; }
        float s = 0.f;
#pragma unroll
        for (int e = 0; e < E; e++) s += expf(acc[e] - m);
        g_expert_idx[warp] = bi;
        g_gate[warp]       = 1.f / s;
    }
}

// ---------------- kernel 2: order-preserving scan (warp-shuffle) ----------------
__global__ void scan_kernel() {
    __shared__ unsigned long long w0[32], w1[32];
    const int tid = threadIdx.x;
    const int lane = tid & 31, wid = tid >> 5;

    const int base = tid * 8;
    int eidx[8];
    unsigned long long c0 = 0ULL, c1 = 0ULL;
#pragma unroll
    for (int j = 0; j < 8; j++) {
        int e = g_expert_idx[base + j];
        eidx[j] = e;
        if (e < 4) c0 += 1ULL << (16 * e);
        else       c1 += 1ULL << (16 * (e - 4));
    }
    unsigned long long s0 = c0, s1 = c1;
#pragma unroll
    for (int d = 1; d < 32; d <<= 1) {
        unsigned long long t0 = __shfl_up_sync(0xffffffffu, s0, d);
        unsigned long long t1 = __shfl_up_sync(0xffffffffu, s1, d);
        if (lane >= d) { s0 += t0; s1 += t1; }
    }
    if (lane == 31) { w0[wid] = s0; w1[wid] = s1; }

    for (int i = tid; i < E * CAP; i += 1024) g_slot_token[i] = -1;
    __syncthreads();
    if (wid == 0) {
        unsigned long long v0 = w0[lane], v1 = w1[lane];
#pragma unroll
        for (int d = 1; d < 32; d <<= 1) {
            unsigned long long t0 = __shfl_up_sync(0xffffffffu, v0, d);
            unsigned long long t1 = __shfl_up_sync(0xffffffffu, v1, d);
            if (lane >= d) { v0 += t0; v1 += t1; }
        }
        w0[lane] = v0; w1[lane] = v1;
    }
    __syncthreads();
    unsigned long long o0 = s0 - c0 + (wid > 0 ? w0[wid - 1] : 0ULL);
    unsigned long long o1 = s1 - c1 + (wid > 0 ? w1[wid - 1] : 0ULL);

    int off[E];
#pragma unroll
    for (int e = 0; e < 4; e++) {
        off[e]     = (int)((o0 >> (16 * e)) & 0xFFFFULL);
        off[e + 4] = (int)((o1 >> (16 * e)) & 0xFFFFULL);
    }
#pragma unroll
    for (int j = 0; j < 8; j++) {
        int t = base + j;
        int e = eidx[j];
        int p = 0;
#pragma unroll
        for (int q = 0; q < E; q++)
            if (e == q) { p = off[q]; off[q] = p + 1; }
        if (p < CAP) { g_slot_token[e * CAP + p] = t; g_dropped[t] = 0; }
        else         { g_dropped[t] = 1; }
    }
}

// ---------------- kernel 3: convert W -> fp16 + zero dropped rows ----------------
// blocks [0, 2048): W (16 elems/thread, 256 thr); [2048, 10240): dropped-token zeroing
__global__ void convW_kernel(const float* __restrict__ W, float* __restrict__ out) {
    int bid = blockIdx.x;
    int tid = threadIdx.x;
    if (bid < 2048) {
        size_t base = ((size_t)bid * 256 + tid) * 16;
        float4 a0 = *(const float4*)(W + base);
        float4 a1 = *(const float4*)(W + base + 4);
        float4 a2 = *(const float4*)(W + base + 8);
        float4 a3 = *(const float4*)(W + base + 12);
        float v[16] = {a0.x,a0.y,a0.z,a0.w, a1.x,a1.y,a1.z,a1.w,
                       a2.x,a2.y,a2.z,a2.w, a3.x,a3.y,a3.z,a3.w};
        __half h[16];
#pragma unroll
        for (int i = 0; i < 16; i++) h[i] = __float2half_rn(v[i]);
        *(uint4*)(g_Wh + base)     = ((uint4*)h)[0];
        *(uint4*)(g_Wh + base + 8) = ((uint4*)h)[1];
    } else {
        int t = bid - 2048;
        if (!g_dropped[t]) return;
        float4* row = (float4*)(out + (size_t)t * H);
        row[tid] = make_float4(0.f, 0.f, 0.f, 0.f);
    }
}

// ---------------- kernel 4: GEMM, single-term fp16, 2 planes, 4-stage cp.async ----------------
#define BM 128
#define BN 128
#define BK 64                      // fp16 per chunk = 128B rows
#define KITER (H / BK)             // 16
#define ROW_B 128                  // bytes per smem row
#define PLANE_B (BM * ROW_B)       // 16384
#define STAGE_B (2 * PLANE_B)      // 32768
#define NSTAGE 4
#define SMEM_TOK 512
#define GEMM_SMEM (SMEM_TOK + NSTAGE * STAGE_B)   // 131584

__device__ __forceinline__ uint32_t smem_u32(const void* p) {
    uint32_t a;
    asm("{ .reg .u64 t; cvta.to.shared.u64 t, %1; cvt.u32.u64 %0, t; }" : "=r"(a) : "l"(p));
    return a;
}
__device__ __forceinline__ void cpasync16(uint32_t dst, const void* src) {
    asm volatile("cp.async.cg.shared.global [%0], [%1], 16;" :: "r"(dst), "l"(src));
}
__device__ __forceinline__ void cpasync16z(uint32_t dst, const void* src, uint32_t sz) {
    asm volatile("cp.async.cg.shared.global [%0], [%1], 16, %2;" :: "r"(dst), "l"(src), "r"(sz));
}
__device__ __forceinline__ void ldsm4(uint32_t& r0, uint32_t& r1, uint32_t& r2, uint32_t& r3,
                                      uint32_t addr) {
    asm volatile("ldmatrix.sync.aligned.m8n8.x4.shared.b16 {%0,%1,%2,%3}, [%4];"
                 : "=r"(r0), "=r"(r1), "=r"(r2), "=r"(r3) : "r"(addr));
}
__device__ __forceinline__ void mma16816(float* d, const uint32_t* a, uint32_t b0, uint32_t b1) {
    asm volatile("mma.sync.aligned.m16n8k16.row.col.f32.f16.f16.f32 "
                 "{%0,%1,%2,%3}, {%4,%5,%6,%7}, {%8,%9}, {%0,%1,%2,%3};"
                 : "+f"(d[0]), "+f"(d[1]), "+f"(d[2]), "+f"(d[3])
                 : "r"(a[0]), "r"(a[1]), "r"(a[2]), "r"(a[3]), "r"(b0), "r"(b1));
}

__global__ void __launch_bounds__(512, 1)
moe_gemm(const float* __restrict__ bias, float* __restrict__ out) {
    extern __shared__ char smem[];
    int* s_tok = (int*)smem;
    const uint32_t sbase = smem_u32(smem) + SMEM_TOK;

    const int tid  = threadIdx.x;
    const int lane = tid & 31;
    const int wid  = tid >> 5;             // 0..15, warp grid 4(M) x 4(N)
    const int bm = blockIdx.y * BM;
    const int bn = blockIdx.x * BN;
    const int e  = bm >> 10;

    if (tid < BM) s_tok[tid] = g_slot_token[bm + tid];

    // ---- cp.async mapping: row = tid>>2 (4 thr/row), 2 x 16B segs each ----
    const int crow = tid >> 2;
    const int s0   = (tid & 3) * 2;
    const uint32_t d0 = (uint32_t)(crow * ROW_B + ((s0     ^ (crow & 7)) * 16));
    const uint32_t d1 = (uint32_t)(crow * ROW_B + (((s0+1) ^ (crow & 7)) * 16));
    // A is gathered straight from g_xh by token id; empty slot -> zero-fill copy
    const int atok = g_slot_token[bm + crow];
    const uint32_t asz = (atok >= 0) ? 16u : 0u;
    const __half* pA  = g_xh + (size_t)(atok >= 0 ? atok : 0) * H + s0 * 8;
    const __half* pB  = g_Wh + ((size_t)e * H + bn + crow) * H + s0 * 8;

#define ISSUE_STAGE(stg, kc) do { \
        uint32_t db = sbase + (stg) * STAGE_B; \
        int ko = (kc) * BK; \
        cpasync16z(db + d0,            pA + ko,     asz); \
        cpasync16z(db + d1,            pA + ko + 8, asz); \
        cpasync16(db + PLANE_B + d0,   pB + ko); \
        cpasync16(db + PLANE_B + d1,   pB + ko + 8); \
        asm volatile("cp.async.commit_group;" ::: "memory"); \
    } while (0)

    float D[2][4][4];
#pragma unroll
    for (int mt = 0; mt < 2; mt++)
#pragma unroll
        for (int nt = 0; nt < 4; nt++)
#pragma unroll
            for (int r = 0; r < 4; r++) D[mt][nt][r] = 0.f;

    const int mrow = (wid >> 2) * 32 + (lane & 15);   // + mt*16
    const int nrow = (wid & 3) * 32 + (lane & 15);    // + np*16
    const int chalf = lane >> 4;                      // 16B half within k16

    // hoisted swizzled ldsm offsets (stage-relative), indexed by compile-time ks
    uint32_t swzA[2][4], swzB[2][4];
#pragma unroll
    for (int mt = 0; mt < 2; mt++) {
        int r = mrow + mt * 16;
#pragma unroll
        for (int ks = 0; ks < 4; ks++)
            swzA[mt][ks] = (uint32_t)(r * ROW_B + (((ks * 2 + chalf) ^ (r & 7)) << 4));
    }
#pragma unroll
    for (int np = 0; np < 2; np++) {
        int r = nrow + np * 16;
#pragma unroll
        for (int ks = 0; ks < 4; ks++)
            swzB[np][ks] = (uint32_t)(PLANE_B + r * ROW_B + (((ks * 2 + chalf) ^ (r & 7)) << 4));
    }

#define LOAD_FRAGS(ks_, b_) do { \
        ldsm4(fa[b_][0][0], fa[b_][0][1], fa[b_][0][2], fa[b_][0][3], ab + swzA[0][ks_]); \
        ldsm4(fa[b_][1][0], fa[b_][1][1], fa[b_][1][2], fa[b_][1][3], ab + swzA[1][ks_]); \
        ldsm4(fb[b_][0][0], fb[b_][0][1], fb[b_][0][2], fb[b_][0][3], ab + swzB[0][ks_]); \
        ldsm4(fb[b_][1][0], fb[b_][1][1], fb[b_][1][2], fb[b_][1][3], ab + swzB[1][ks_]); \
    } while (0)

    // prologue: 3 of 4 stages in flight
    ISSUE_STAGE(0, 0);
    ISSUE_STAGE(1, 1);
    ISSUE_STAGE(2, 2);

#pragma unroll 1
    for (int kb = 0; kb < KITER; kb += NSTAGE) {
#pragma unroll
        for (int s = 0; s < NSTAGE; s++) {
            const int kc = kb + s;
            if (kc < KITER - 2)       asm volatile("cp.async.wait_group 2;" ::: "memory");
            else if (kc == KITER - 2) asm volatile("cp.async.wait_group 1;" ::: "memory");
            else                      asm volatile("cp.async.wait_group 0;" ::: "memory");
            __syncthreads();   // proves all warps finished stage (s+3)&3 reads

            if (kc + 3 < KITER) ISSUE_STAGE((s + 3) & 3, kc + 3);

            const uint32_t ab = sbase + s * STAGE_B;   // compile-time stage offset
            uint32_t fa[2][2][4], fb[2][2][4];
            LOAD_FRAGS(0, 0);
#pragma unroll
            for (int ks = 0; ks < 4; ks++) {
                const int cur = ks & 1;
                if (ks == 0)      LOAD_FRAGS(1, 1);
                else if (ks == 1) LOAD_FRAGS(2, 0);
                else if (ks == 2) LOAD_FRAGS(3, 1);
#pragma unroll
                for (int mt = 0; mt < 2; mt++)
#pragma unroll
                    for (int nt = 0; nt < 4; nt++) {
                        int np = nt >> 1, od = nt & 1;
                        mma16816(D[mt][nt], fa[cur][mt], fb[cur][np][od], fb[cur][np][2 + od]);
                    }
            }
        }
    }

    // ---- epilogue: gate * (D + bias) scattered to token rows ----
    const int wm = (wid >> 2) * 32;
    const int wn = (wid & 3) * 32;
#pragma unroll
    for (int mt = 0; mt < 2; mt++) {
#pragma unroll
        for (int half = 0; half < 2; half++) {
            int r = wm + mt * 16 + (lane >> 2) + half * 8;
            int tok = s_tok[r];
            if (tok < 0) continue;
            float g = g_gate[tok];
            float* orow = out + (size_t)tok * H + bn + wn;
#pragma unroll
            for (int nt = 0; nt < 4; nt++) {
                int c = nt * 8 + (lane & 3) * 2;
                float2 bb = *(const float2*)(bias + (size_t)e * H + bn + wn + c);
                float2 v;
                v.x = g * (D[mt][nt][half * 2 + 0] + bb.x);
                v.y = g * (D[mt][nt][half * 2 + 1] + bb.y);
                *(float2*)(orow + c) = v;
            }
        }
    }
}

extern "C" void kernel_launch(void* const* d_in, const int* in_sizes, int n_in,
                              void* d_out, int out_size) {
    const float* x  = (const float*)d_in[0];   // [T, H]
    const float* wg = (const float*)d_in[1];   // [H, E]
    const float* W  = (const float*)d_in[2];   // [E, H, H]
    const float* b  = (const float*)d_in[3];   // [E, H]
    float* out = (float*)d_out;                // [T, H]

    cudaFuncSetAttribute(moe_gemm, cudaFuncAttributeMaxDynamicSharedMemorySize, GEMM_SMEM);

    route_kernel<<<T_TOK / 8, 256>>>(x, wg);
    scan_kernel<<<1, 1024>>>();
    convW_kernel<<<2048 + T_TOK, 256>>>(W, out);
    dim3 grid(H / BN, T_TOK / BM);             // (8, 64)
    moe_gemm<<<grid, 512, GEMM_SMEM>>>(b, out);
}

// round 16
// speedup vs baseline: 1.9914x; 1.0297x over previous
#include <cuda_runtime.h>
#include <cuda_fp16.h>
#include <math.h>
#include <stdint.h>

#define T_TOK 8192
#define H 1024
#define E 8
#define CAP 1024   // capacity = T/E

// ---------------- scratch (no allocations allowed) ----------------
__device__ int   g_expert_idx[T_TOK];
__device__ float g_gate[T_TOK];
__device__ int   g_slot_token[E * CAP];   // token id per (expert, slot), -1 if empty
__device__ unsigned char g_dropped[T_TOK];
__device__ __align__(256) __half g_Wh[E * H * H];    // 16 MB (fp16 W)
__device__ __align__(256) __half g_xh[T_TOK * H];    // 16 MB (fp16 x, token order)

// ---------------- kernel 1: fused routing (+fp16 x) and W->fp16 conversion ----------------
// blocks [0, 1024): routing, 8 warps = 8 tokens per block
// blocks [1024, 3072): W conversion, 16 elems/thread
__global__ void route_conv_kernel(const float* __restrict__ x,
                                  const float* __restrict__ wg,
                                  const float* __restrict__ W) {
    if (blockIdx.x >= 1024) {
        // ---- W conversion part (independent of routing) ----
        size_t base = ((size_t)(blockIdx.x - 1024) * 256 + threadIdx.x) * 16;
        float4 a0 = *(const float4*)(W + base);
        float4 a1 = *(const float4*)(W + base + 4);
        float4 a2 = *(const float4*)(W + base + 8);
        float4 a3 = *(const float4*)(W + base + 12);
        float v[16] = {a0.x,a0.y,a0.z,a0.w, a1.x,a1.y,a1.z,a1.w,
                       a2.x,a2.y,a2.z,a2.w, a3.x,a3.y,a3.z,a3.w};
        __half h[16];
#pragma unroll
        for (int i = 0; i < 16; i++) h[i] = __float2half_rn(v[i]);
        *(uint4*)(g_Wh + base)     = ((uint4*)h)[0];
        *(uint4*)(g_Wh + base + 8) = ((uint4*)h)[1];
        return;
    }

    // ---- routing part ----
    __shared__ float s_wg[H * E];
    for (int i = threadIdx.x; i < H * E; i += blockDim.x) s_wg[i] = wg[i];
    __syncthreads();

    int warp = (blockIdx.x * blockDim.x + threadIdx.x) >> 5;
    int lane = threadIdx.x & 31;

    const float* xp = x + (size_t)warp * H;
    __half* xh = g_xh + (size_t)warp * H;
    float acc[E];
#pragma unroll
    for (int e = 0; e < E; e++) acc[e] = 0.f;
    for (int k = lane; k < H; k += 32) {
        float xv = xp[k];
        xh[k] = __float2half_rn(xv);          // emit fp16 copy (A-conv fused)
        const float* w = s_wg + k * E;
#pragma unroll
        for (int e = 0; e < E; e++) acc[e] = fmaf(xv, w[e], acc[e]);
    }
#pragma unroll
    for (int e = 0; e < E; e++) {
#pragma unroll
        for (int o = 16; o > 0; o >>= 1)
            acc[e] += __shfl_down_sync(0xffffffffu, acc[e], o);
    }
    if (lane == 0) {
        float m = acc[0]; int bi = 0;
#pragma unroll
        for (int e = 1; e < E; e++)
            if (acc[e] > m) { m = acc[e]; bi = e; }
        float s = 0.f;
#pragma unroll
        for (int e = 0; e < E; e++) s += expf(acc[e] - m);
        g_expert_idx[warp] = bi;
        g_gate[warp]       = 1.f / s;
    }
}

// ---------------- kernel 2: order-preserving scan (warp-shuffle) ----------------
__global__ void scan_kernel() {
    __shared__ unsigned long long w0[32], w1[32];
    const int tid = threadIdx.x;
    const int lane = tid & 31, wid = tid >> 5;

    const int base = tid * 8;
    int eidx[8];
    unsigned long long c0 = 0ULL, c1 = 0ULL;
#pragma unroll
    for (int j = 0; j < 8; j++) {
        int e = g_expert_idx[base + j];
        eidx[j] = e;
        if (e < 4) c0 += 1ULL << (16 * e);
        else       c1 += 1ULL << (16 * (e - 4));
    }
    unsigned long long s0 = c0, s1 = c1;
#pragma unroll
    for (int d = 1; d < 32; d <<= 1) {
        unsigned long long t0 = __shfl_up_sync(0xffffffffu, s0, d);
        unsigned long long t1 = __shfl_up_sync(0xffffffffu, s1, d);
        if (lane >= d) { s0 += t0; s1 += t1; }
    }
    if (lane == 31) { w0[wid] = s0; w1[wid] = s1; }

    for (int i = tid; i < E * CAP; i += 1024) g_slot_token[i] = -1;
    __syncthreads();
    if (wid == 0) {
        unsigned long long v0 = w0[lane], v1 = w1[lane];
#pragma unroll
        for (int d = 1; d < 32; d <<= 1) {
            unsigned long long t0 = __shfl_up_sync(0xffffffffu, v0, d);
            unsigned long long t1 = __shfl_up_sync(0xffffffffu, v1, d);
            if (lane >= d) { v0 += t0; v1 += t1; }
        }
        w0[lane] = v0; w1[lane] = v1;
    }
    __syncthreads();
    unsigned long long o0 = s0 - c0 + (wid > 0 ? w0[wid - 1] : 0ULL);
    unsigned long long o1 = s1 - c1 + (wid > 0 ? w1[wid - 1] : 0ULL);

    int off[E];
#pragma unroll
    for (int e = 0; e < 4; e++) {
        off[e]     = (int)((o0 >> (16 * e)) & 0xFFFFULL);
        off[e + 4] = (int)((o1 >> (16 * e)) & 0xFFFFULL);
    }
#pragma unroll
    for (int j = 0; j < 8; j++) {
        int t = base + j;
        int e = eidx[j];
        int p = 0;
#pragma unroll
        for (int q = 0; q < E; q++)
            if (e == q) { p = off[q]; off[q] = p + 1; }
        if (p < CAP) { g_slot_token[e * CAP + p] = t; g_dropped[t] = 0; }
        else         { g_dropped[t] = 1; }
    }
}

// ---------------- kernel 3: zero dropped-token output rows ----------------
__global__ void zero_drop_kernel(float* __restrict__ out) {
    int t = blockIdx.x;
    if (!g_dropped[t]) return;
    float4* row = (float4*)(out + (size_t)t * H);
    row[threadIdx.x] = make_float4(0.f, 0.f, 0.f, 0.f);
}

// ---------------- kernel 4: GEMM, single-term fp16, 2-chunk stages, 3-stage ring ----------------
#define BM 128
#define BN 128
#define BK 64                       // fp16 per chunk = 128B rows
#define ROW_B 128                   // bytes per smem row
#define PLANE_B (BM * ROW_B)        // 16384
#define CHUNK_B (2 * PLANE_B)       // 32768 (A plane + B plane)
#define STAGE_B (2 * CHUNK_B)       // 65536 (2 chunks per stage)
#define NSTAGE 3
#define NITER 8                     // H / (2*BK)
#define SMEM_TOK 512
#define GEMM_SMEM (SMEM_TOK + NSTAGE * STAGE_B)   // 197120

__device__ __forceinline__ uint32_t smem_u32(const void* p) {
    uint32_t a;
    asm("{ .reg .u64 t; cvta.to.shared.u64 t, %1; cvt.u32.u64 %0, t; }" : "=r"(a) : "l"(p));
    return a;
}
__device__ __forceinline__ void cpasync16(uint32_t dst, const void* src) {
    asm volatile("cp.async.cg.shared.global [%0], [%1], 16;" :: "r"(dst), "l"(src));
}
__device__ __forceinline__ void cpasync16z(uint32_t dst, const void* src, uint32_t sz) {
    asm volatile("cp.async.cg.shared.global [%0], [%1], 16, %2;" :: "r"(dst), "l"(src), "r"(sz));
}
__device__ __forceinline__ void ldsm4(uint32_t& r0, uint32_t& r1, uint32_t& r2, uint32_t& r3,
                                      uint32_t addr) {
    asm volatile("ldmatrix.sync.aligned.m8n8.x4.shared.b16 {%0,%1,%2,%3}, [%4];"
                 : "=r"(r0), "=r"(r1), "=r"(r2), "=r"(r3) : "r"(addr));
}
__device__ __forceinline__ void mma16816(float* d, const uint32_t* a, uint32_t b0, uint32_t b1) {
    asm volatile("mma.sync.aligned.m16n8k16.row.col.f32.f16.f16.f32 "
                 "{%0,%1,%2,%3}, {%4,%5,%6,%7}, {%8,%9}, {%0,%1,%2,%3};"
                 : "+f"(d[0]), "+f"(d[1]), "+f"(d[2]), "+f"(d[3])
                 : "r"(a[0]), "r"(a[1]), "r"(a[2]), "r"(a[3]), "r"(b0), "r"(b1));
}

__global__ void __launch_bounds__(512, 1)
moe_gemm(const float* __restrict__ bias, float* __restrict__ out) {
    extern __shared__ char smem[];
    int* s_tok = (int*)smem;
    const uint32_t sbase = smem_u32(smem) + SMEM_TOK;

    const int tid  = threadIdx.x;
    const int lane = tid & 31;
    const int wid  = tid >> 5;             // 0..15, warp grid 4(M) x 4(N)
    const int bm = blockIdx.y * BM;
    const int bn = blockIdx.x * BN;
    const int e  = bm >> 10;

    if (tid < BM) s_tok[tid] = g_slot_token[bm + tid];

    // ---- cp.async mapping: row = tid>>2 (4 thr/row), 2 x 16B segs each ----
    const int crow = tid >> 2;
    const int s0   = (tid & 3) * 2;
    const uint32_t d0 = (uint32_t)(crow * ROW_B + ((s0     ^ (crow & 7)) * 16));
    const uint32_t d1 = (uint32_t)(crow * ROW_B + (((s0+1) ^ (crow & 7)) * 16));
    const int atok = g_slot_token[bm + crow];
    const uint32_t asz = (atok >= 0) ? 16u : 0u;
    const __half* pA  = g_xh + (size_t)(atok >= 0 ? atok : 0) * H + s0 * 8;
    const __half* pB  = g_Wh + ((size_t)e * H + bn + crow) * H + s0 * 8;

// stage = 2 chunks: [A0|B0|A1|B1], one commit per stage
#define ISSUE_STAGE(stg, it) do { \
        uint32_t db = sbase + (stg) * STAGE_B; \
        int ko = (it) * (2 * BK); \
        cpasync16z(db + d0,                      pA + ko,          asz); \
        cpasync16z(db + d1,                      pA + ko + 8,      asz); \
        cpasync16(db + PLANE_B + d0,             pB + ko); \
        cpasync16(db + PLANE_B + d1,             pB + ko + 8); \
        cpasync16z(db + CHUNK_B + d0,            pA + ko + BK,     asz); \
        cpasync16z(db + CHUNK_B + d1,            pA + ko + BK + 8, asz); \
        cpasync16(db + CHUNK_B + PLANE_B + d0,   pB + ko + BK); \
        cpasync16(db + CHUNK_B + PLANE_B + d1,   pB + ko + BK + 8); \
        asm volatile("cp.async.commit_group;" ::: "memory"); \
    } while (0)

    float D[2][4][4];
#pragma unroll
    for (int mt = 0; mt < 2; mt++)
#pragma unroll
        for (int nt = 0; nt < 4; nt++)
#pragma unroll
            for (int r = 0; r < 4; r++) D[mt][nt][r] = 0.f;

    const int mrow = (wid >> 2) * 32 + (lane & 15);   // + mt*16
    const int nrow = (wid & 3) * 32 + (lane & 15);    // + np*16
    const int chalf = lane >> 4;                      // 16B half within k16

    // hoisted swizzled ldsm offsets (chunk-relative), indexed by compile-time ks&3
    uint32_t swzA[2][4], swzB[2][4];
#pragma unroll
    for (int mt = 0; mt < 2; mt++) {
        int r = mrow + mt * 16;
#pragma unroll
        for (int ks = 0; ks < 4; ks++)
            swzA[mt][ks] = (uint32_t)(r * ROW_B + (((ks * 2 + chalf) ^ (r & 7)) << 4));
    }
#pragma unroll
    for (int np = 0; np < 2; np++) {
        int r = nrow + np * 16;
#pragma unroll
        for (int ks = 0; ks < 4; ks++)
            swzB[np][ks] = (uint32_t)(PLANE_B + r * ROW_B + (((ks * 2 + chalf) ^ (r & 7)) << 4));
    }

// ks_ in [0,8): chunk = ks_>>2, sub-k = ks_&3
#define LOAD_FRAGS(ks_, b_) do { \
        const uint32_t cb = ab + ((ks_) >> 2) * CHUNK_B; \
        ldsm4(fa[b_][0][0], fa[b_][0][1], fa[b_][0][2], fa[b_][0][3], cb + swzA[0][(ks_) & 3]); \
        ldsm4(fa[b_][1][0], fa[b_][1][1], fa[b_][1][2], fa[b_][1][3], cb + swzA[1][(ks_) & 3]); \
        ldsm4(fb[b_][0][0], fb[b_][0][1], fb[b_][0][2], fb[b_][0][3], cb + swzB[0][(ks_) & 3]); \
        ldsm4(fb[b_][1][0], fb[b_][1][1], fb[b_][1][2], fb[b_][1][3], cb + swzB[1][(ks_) & 3]); \
    } while (0)

    // prologue: 2 of 3 stages in flight (4 chunks)
    ISSUE_STAGE(0, 0);
    ISSUE_STAGE(1, 1);

#pragma unroll
    for (int it = 0; it < NITER; it++) {
        const int s = it % NSTAGE;                    // compile-time under full unroll
        if (it < NITER - 1) asm volatile("cp.async.wait_group 1;" ::: "memory");
        else                asm volatile("cp.async.wait_group 0;" ::: "memory");
        __syncthreads();   // proves all warps finished reading stage (it+2)%3 last iter

        if (it + 2 < NITER) ISSUE_STAGE((it + 2) % NSTAGE, it + 2);

        const uint32_t ab = sbase + s * STAGE_B;
        uint32_t fa[2][2][4], fb[2][2][4];
        LOAD_FRAGS(0, 0);
#pragma unroll
        for (int ks = 0; ks < 8; ks++) {
            const int cur = ks & 1;
            if (ks < 7) {
                switch (ks) {
                    case 0: LOAD_FRAGS(1, 1); break;
                    case 1: LOAD_FRAGS(2, 0); break;
                    case 2: LOAD_FRAGS(3, 1); break;
                    case 3: LOAD_FRAGS(4, 0); break;
                    case 4: LOAD_FRAGS(5, 1); break;
                    case 5: LOAD_FRAGS(6, 0); break;
                    default: LOAD_FRAGS(7, 1); break;
                }
            }
#pragma unroll
            for (int mt = 0; mt < 2; mt++)
#pragma unroll
                for (int nt = 0; nt < 4; nt++) {
                    int np = nt >> 1, od = nt & 1;
                    mma16816(D[mt][nt], fa[cur][mt], fb[cur][np][od], fb[cur][np][2 + od]);
                }
        }
    }

    // ---- epilogue: gate * (D + bias) scattered to token rows ----
    const int wm = (wid >> 2) * 32;
    const int wn = (wid & 3) * 32;
#pragma unroll
    for (int mt = 0; mt < 2; mt++) {
#pragma unroll
        for (int half = 0; half < 2; half++) {
            int r = wm + mt * 16 + (lane >> 2) + half * 8;
            int tok = s_tok[r];
            if (tok < 0) continue;
            float g = g_gate[tok];
            float* orow = out + (size_t)tok * H + bn + wn;
#pragma unroll
            for (int nt = 0; nt < 4; nt++) {
                int c = nt * 8 + (lane & 3) * 2;
                float2 bb = *(const float2*)(bias + (size_t)e * H + bn + wn + c);
                float2 v;
                v.x = g * (D[mt][nt][half * 2 + 0] + bb.x);
                v.y = g * (D[mt][nt][half * 2 + 1] + bb.y);
                *(float2*)(orow + c) = v;
            }
        }
    }
}

extern "C" void kernel_launch(void* const* d_in, const int* in_sizes, int n_in,
                              void* d_out, int out_size) {
    const float* x  = (const float*)d_in[0];   // [T, H]
    const float* wg = (const float*)d_in[1];   // [H, E]
    const float* W  = (const float*)d_in[2];   // [E, H, H]
    const float* b  = (const float*)d_in[3];   // [E, H]
    float* out = (float*)d_out;                // [T, H]

    cudaFuncSetAttribute(moe_gemm, cudaFuncAttributeMaxDynamicSharedMemorySize, GEMM_SMEM);

    route_conv_kernel<<<3072, 256>>>(x, wg, W);   // routing + W conversion overlapped
    scan_kernel<<<1, 1024>>>();
    zero_drop_kernel<<<T_TOK, 256>>>(out);
    dim3 grid(H / BN, T_TOK / BM);                // (8, 64)
    moe_gemm<<<grid, 512, GEMM_SMEM>>>(b, out);
}